// round 1
// baseline (speedup 1.0000x reference)
#include <cuda_runtime.h>
#include <stdint.h>

// Problem constants
#define BB 16
#define CC 4
#define HH 512
#define WW 1024
#define ROWS (BB * CC * HH)       // 32768
#define BCN  (BB * CC)            // 64

// Scratch: per-row masked abs error (128 KB, static device memory — no allocs)
__device__ float g_abs_err[ROWS];

// ---------------------------------------------------------------------------
// Kernel 1: one warp per row. Argmax over W=1024 of cls_true (first-max
// semantics), gather offset_pred/offset_true at that index, apply vertical
// mask, store |p - t| * mask per row.
// ---------------------------------------------------------------------------
__global__ __launch_bounds__(256) void row_argmax_kernel(
    const float* __restrict__ offset_pred,
    const float* __restrict__ offset_true,
    const float* __restrict__ cls_true,
    const float* __restrict__ vertical_true)
{
    const int warp_in_block = threadIdx.x >> 5;
    const int lane = threadIdx.x & 31;
    const int row = blockIdx.x * 8 + warp_in_block;   // 8 warps/block
    if (row >= ROWS) return;

    const float4* crow = reinterpret_cast<const float4*>(cls_true + (size_t)row * WW);

    // Each lane scans 8 float4 = 32 elements, in increasing index order so that
    // strictly-greater comparison keeps the FIRST max within the lane.
    float best = -__int_as_float(0x7f800000);  // -inf
    int   bidx = 0;

#pragma unroll
    for (int k = 0; k < 8; k++) {
        const int vec_elem = k * 32 + lane;          // float4 index within row
        float4 v = __ldg(&crow[vec_elem]);
        const int base = vec_elem * 4;
        if (v.x > best) { best = v.x; bidx = base + 0; }
        if (v.y > best) { best = v.y; bidx = base + 1; }
        if (v.z > best) { best = v.z; bidx = base + 2; }
        if (v.w > best) { best = v.w; bidx = base + 3; }
    }

    // Warp reduction: prefer larger value; on exact tie prefer smaller index
    // (first-max, matching jnp.argmax / torch.argmax).
#pragma unroll
    for (int off = 16; off > 0; off >>= 1) {
        float oval = __shfl_xor_sync(0xffffffffu, best, off);
        int   oidx = __shfl_xor_sync(0xffffffffu, bidx, off);
        if (oval > best || (oval == best && oidx < bidx)) {
            best = oval;
            bidx = oidx;
        }
    }

    if (lane == 0) {
        const size_t gidx = (size_t)row * WW + bidx;
        float p = __ldg(&offset_pred[gidx]);
        float t = __ldg(&offset_true[gidx]);
        float mask = (__ldg(&vertical_true[row]) >= 0.5f) ? 1.0f : 0.0f;
        g_abs_err[row] = fabsf(p - t) * mask;
    }
}

// ---------------------------------------------------------------------------
// Kernel 2: zero the output scalar (d_out is poisoned to 0xAA).
// ---------------------------------------------------------------------------
__global__ void zero_out_kernel(float* out) { out[0] = 0.0f; }

// ---------------------------------------------------------------------------
// Kernel 3: one block per (b,c). Block-reduce sum of abs_err and count of
// masked rows over H=512, then atomicAdd(per_bc / B) into the scalar output.
// ---------------------------------------------------------------------------
__global__ __launch_bounds__(512) void bc_reduce_kernel(
    const float* __restrict__ vertical_true,
    float* __restrict__ out)
{
    const int bc = blockIdx.x;          // 0..63
    const int t  = threadIdx.x;         // 0..511
    const int row = bc * HH + t;

    float err = g_abs_err[row];
    float cnt = (__ldg(&vertical_true[row]) >= 0.5f) ? 1.0f : 0.0f;

    // Warp reduce
#pragma unroll
    for (int off = 16; off > 0; off >>= 1) {
        err += __shfl_xor_sync(0xffffffffu, err, off);
        cnt += __shfl_xor_sync(0xffffffffu, cnt, off);
    }

    __shared__ float s_err[16];
    __shared__ float s_cnt[16];
    const int wid = t >> 5;
    const int lane = t & 31;
    if (lane == 0) { s_err[wid] = err; s_cnt[wid] = cnt; }
    __syncthreads();

    if (wid == 0) {
        err = (lane < 16) ? s_err[lane] : 0.0f;
        cnt = (lane < 16) ? s_cnt[lane] : 0.0f;
#pragma unroll
        for (int off = 8; off > 0; off >>= 1) {
            err += __shfl_xor_sync(0xffffffffu, err, off);
            cnt += __shfl_xor_sync(0xffffffffu, cnt, off);
        }
        if (lane == 0) {
            float per_bc = (cnt > 0.0f) ? (err / fmaxf(cnt, 1.0f)) : 0.0f;
            atomicAdd(out, per_bc / (float)BB);
        }
    }
}

// ---------------------------------------------------------------------------
extern "C" void kernel_launch(void* const* d_in, const int* in_sizes, int n_in,
                              void* d_out, int out_size)
{
    const float* offset_pred   = (const float*)d_in[0];
    const float* offset_true   = (const float*)d_in[1];
    const float* cls_true      = (const float*)d_in[2];
    const float* vertical_true = (const float*)d_in[3];
    float* out = (float*)d_out;

    zero_out_kernel<<<1, 1>>>(out);

    // 32768 rows, 8 warps (rows) per block of 256 threads -> 4096 blocks
    row_argmax_kernel<<<ROWS / 8, 256>>>(offset_pred, offset_true, cls_true,
                                         vertical_true);

    bc_reduce_kernel<<<BCN, 512>>>(vertical_true, out);
}

// round 2
// speedup vs baseline: 1.0708x; 1.0708x over previous
#include <cuda_runtime.h>
#include <stdint.h>

// Problem constants
#define BB 16
#define CC 4
#define HH 512
#define WW 1024
#define ROWS (BB * CC * HH)       // 32768
#define BCN  (BB * CC)            // 64

// Scratch: per-row masked abs error (128 KB, static device memory — no allocs)
__device__ float g_abs_err[ROWS];

// ---------------------------------------------------------------------------
// Kernel 1: one warp per row. Argmax over W=1024 of cls_true (first-max
// semantics), gather offset_pred/offset_true at that index, apply vertical
// mask, store |p - t| * mask per row.
//
// Loads are front-batched (8x float4 issued before any compare) to maximize
// MLP, and use streaming hint (.cs) since cls_true is touched exactly once.
// ---------------------------------------------------------------------------
__global__ __launch_bounds__(256) void row_argmax_kernel(
    const float* __restrict__ offset_pred,
    const float* __restrict__ offset_true,
    const float* __restrict__ cls_true,
    const float* __restrict__ vertical_true)
{
    const int warp_in_block = threadIdx.x >> 5;
    const int lane = threadIdx.x & 31;
    const int row = blockIdx.x * 8 + warp_in_block;   // 8 warps/block

    const float4* crow = reinterpret_cast<const float4*>(cls_true + (size_t)row * WW);

    // Front-batch all 8 coalesced float4 loads (512B/warp each) -> MLP_p1 = 8.
    float4 v[8];
#pragma unroll
    for (int k = 0; k < 8; k++) {
        v[k] = __ldcs(&crow[k * 32 + lane]);   // streaming: read-once data
    }

    // Per-lane scan in increasing index order (first-max within lane).
    float best = -__int_as_float(0x7f800000);  // -inf
    int   bidx = 0;
#pragma unroll
    for (int k = 0; k < 8; k++) {
        const int base = (k * 32 + lane) * 4;
        if (v[k].x > best) { best = v[k].x; bidx = base + 0; }
        if (v[k].y > best) { best = v[k].y; bidx = base + 1; }
        if (v[k].z > best) { best = v[k].z; bidx = base + 2; }
        if (v[k].w > best) { best = v[k].w; bidx = base + 3; }
    }

    // Warp reduction: larger value wins; exact tie -> smaller index (first-max).
#pragma unroll
    for (int off = 16; off > 0; off >>= 1) {
        float oval = __shfl_xor_sync(0xffffffffu, best, off);
        int   oidx = __shfl_xor_sync(0xffffffffu, bidx, off);
        if (oval > best || (oval == best && oidx < bidx)) {
            best = oval;
            bidx = oidx;
        }
    }

    if (lane == 0) {
        const size_t gidx = (size_t)row * WW + bidx;
        float p = __ldg(&offset_pred[gidx]);
        float t = __ldg(&offset_true[gidx]);
        float mask = (__ldg(&vertical_true[row]) >= 0.5f) ? 1.0f : 0.0f;
        g_abs_err[row] = fabsf(p - t) * mask;
    }
}

// ---------------------------------------------------------------------------
// Kernel 2 (finisher): ONE block, 1024 threads = 32 warps. Each warp reduces
// two (b,c) groups of 512 rows each (sum of abs_err + count of masked rows),
// computes per_bc means, block-reduces, writes the scalar. No atomics, no
// separate zero kernel (out is written unconditionally).
// ---------------------------------------------------------------------------
__global__ __launch_bounds__(1024) void final_reduce_kernel(
    const float* __restrict__ vertical_true,
    float* __restrict__ out)
{
    const int t    = threadIdx.x;
    const int warp = t >> 5;           // 0..31
    const int lane = t & 31;

    float acc = 0.0f;                  // sum of per_bc for this warp's groups

#pragma unroll
    for (int g = 0; g < 2; g++) {
        const int bc = warp * 2 + g;   // 0..63
        float err = 0.0f;
        float cnt = 0.0f;
#pragma unroll
        for (int i = 0; i < 16; i++) {
            const int row = bc * HH + i * 32 + lane;
            err += g_abs_err[row];
            cnt += (__ldg(&vertical_true[row]) >= 0.5f) ? 1.0f : 0.0f;
        }
#pragma unroll
        for (int off = 16; off > 0; off >>= 1) {
            err += __shfl_xor_sync(0xffffffffu, err, off);
            cnt += __shfl_xor_sync(0xffffffffu, cnt, off);
        }
        if (lane == 0) {
            acc += (cnt > 0.0f) ? (err / fmaxf(cnt, 1.0f)) : 0.0f;
        }
    }

    __shared__ float s_acc[32];
    if (lane == 0) s_acc[warp] = acc;
    __syncthreads();

    if (warp == 0) {
        float vsum = s_acc[lane];      // 32 warps -> all lanes valid
#pragma unroll
        for (int off = 16; off > 0; off >>= 1) {
            vsum += __shfl_xor_sync(0xffffffffu, vsum, off);
        }
        if (lane == 0) {
            out[0] = vsum / (float)BB;
        }
    }
}

// ---------------------------------------------------------------------------
extern "C" void kernel_launch(void* const* d_in, const int* in_sizes, int n_in,
                              void* d_out, int out_size)
{
    const float* offset_pred   = (const float*)d_in[0];
    const float* offset_true   = (const float*)d_in[1];
    const float* cls_true      = (const float*)d_in[2];
    const float* vertical_true = (const float*)d_in[3];
    float* out = (float*)d_out;

    // 32768 rows, 8 warps (rows) per block of 256 threads -> 4096 blocks
    row_argmax_kernel<<<ROWS / 8, 256>>>(offset_pred, offset_true, cls_true,
                                         vertical_true);

    final_reduce_kernel<<<1, 1024>>>(vertical_true, out);
}

// round 3
// speedup vs baseline: 1.1417x; 1.0662x over previous
#include <cuda_runtime.h>
#include <stdint.h>

// Problem constants
#define BB 16
#define CC 4
#define HH 512
#define WW 1024
#define ROWS (BB * CC * HH)       // 32768
#define NBLK (ROWS / 8)           // 4096 blocks, 8 rows each
#define BCN  (BB * CC)            // 64 (b,c) groups; 64 blocks per group

// Scratch: per-block partial (err_sum, cnt_sum) — 32 KB static device memory.
__device__ float2 g_part[NBLK];

// ---------------------------------------------------------------------------
// Kernel 1: one warp per row. Argmax over W=1024 of cls_true (first-max
// semantics), gather offset_pred/offset_true at that index, apply vertical
// mask. Then block-reduce the 8 rows' (abs_err, mask) into one float2 partial.
// All 8 rows of a block belong to the same (b,c) group (512 rows per group).
// ---------------------------------------------------------------------------
__global__ __launch_bounds__(256) void row_argmax_kernel(
    const float* __restrict__ offset_pred,
    const float* __restrict__ offset_true,
    const float* __restrict__ cls_true,
    const float* __restrict__ vertical_true)
{
    const int warp_in_block = threadIdx.x >> 5;
    const int lane = threadIdx.x & 31;
    const int row = blockIdx.x * 8 + warp_in_block;

    const float4* crow = reinterpret_cast<const float4*>(cls_true + (size_t)row * WW);

    // Front-batch all 8 coalesced float4 loads (512B/warp each) -> MLP 8.
    float4 v[8];
#pragma unroll
    for (int k = 0; k < 8; k++) {
        v[k] = __ldcs(&crow[k * 32 + lane]);   // streaming: read-once data
    }

    // Per-lane scan in increasing index order (first-max within lane).
    float best = -__int_as_float(0x7f800000);  // -inf
    int   bidx = 0;
#pragma unroll
    for (int k = 0; k < 8; k++) {
        const int base = (k * 32 + lane) * 4;
        if (v[k].x > best) { best = v[k].x; bidx = base + 0; }
        if (v[k].y > best) { best = v[k].y; bidx = base + 1; }
        if (v[k].z > best) { best = v[k].z; bidx = base + 2; }
        if (v[k].w > best) { best = v[k].w; bidx = base + 3; }
    }

    // Warp reduction: larger value wins; exact tie -> smaller index (first-max).
#pragma unroll
    for (int off = 16; off > 0; off >>= 1) {
        float oval = __shfl_xor_sync(0xffffffffu, best, off);
        int   oidx = __shfl_xor_sync(0xffffffffu, bidx, off);
        if (oval > best || (oval == best && oidx < bidx)) {
            best = oval;
            bidx = oidx;
        }
    }

    // Lane 0 of each warp: gather + mask for this row.
    __shared__ float s_err[8];
    __shared__ float s_cnt[8];
    if (lane == 0) {
        const size_t gidx = (size_t)row * WW + bidx;
        float p = __ldg(&offset_pred[gidx]);
        float t = __ldg(&offset_true[gidx]);
        float mask = (__ldg(&vertical_true[row]) >= 0.5f) ? 1.0f : 0.0f;
        s_err[warp_in_block] = fabsf(p - t) * mask;
        s_cnt[warp_in_block] = mask;
    }
    __syncthreads();

    // Warp 0, lanes 0..7 hold the 8 row results -> reduce and store partial.
    if (threadIdx.x < 8) {
        float e = s_err[threadIdx.x];
        float c = s_cnt[threadIdx.x];
#pragma unroll
        for (int off = 4; off > 0; off >>= 1) {
            e += __shfl_xor_sync(0x000000ffu, e, off);
            c += __shfl_xor_sync(0x000000ffu, c, off);
        }
        if (threadIdx.x == 0) {
            g_part[blockIdx.x] = make_float2(e, c);
        }
    }
}

// ---------------------------------------------------------------------------
// Kernel 2 (finisher): ONE block, 1024 threads = 32 warps. Each warp reduces
// two (b,c) groups; each group has 64 coalesced float2 partials (2 per lane).
// Total read: 32 KB. Computes per_bc means, block-reduces, writes the scalar.
// ---------------------------------------------------------------------------
__global__ __launch_bounds__(1024) void final_reduce_kernel(float* __restrict__ out)
{
    const int t    = threadIdx.x;
    const int warp = t >> 5;           // 0..31
    const int lane = t & 31;

    float acc = 0.0f;                  // sum of per_bc for this warp's 2 groups

#pragma unroll
    for (int g = 0; g < 2; g++) {
        const int bc = warp * 2 + g;   // 0..63
        float err = 0.0f;
        float cnt = 0.0f;
#pragma unroll
        for (int j = 0; j < 2; j++) {
            float2 p = g_part[bc * 64 + j * 32 + lane];
            err += p.x;
            cnt += p.y;
        }
#pragma unroll
        for (int off = 16; off > 0; off >>= 1) {
            err += __shfl_xor_sync(0xffffffffu, err, off);
            cnt += __shfl_xor_sync(0xffffffffu, cnt, off);
        }
        if (lane == 0) {
            acc += (cnt > 0.0f) ? (err / fmaxf(cnt, 1.0f)) : 0.0f;
        }
    }

    __shared__ float s_acc[32];
    if (lane == 0) s_acc[warp] = acc;
    __syncthreads();

    if (warp == 0) {
        float vsum = s_acc[lane];
#pragma unroll
        for (int off = 16; off > 0; off >>= 1) {
            vsum += __shfl_xor_sync(0xffffffffu, vsum, off);
        }
        if (lane == 0) {
            out[0] = vsum / (float)BB;
        }
    }
}

// ---------------------------------------------------------------------------
extern "C" void kernel_launch(void* const* d_in, const int* in_sizes, int n_in,
                              void* d_out, int out_size)
{
    const float* offset_pred   = (const float*)d_in[0];
    const float* offset_true   = (const float*)d_in[1];
    const float* cls_true      = (const float*)d_in[2];
    const float* vertical_true = (const float*)d_in[3];
    float* out = (float*)d_out;

    row_argmax_kernel<<<NBLK, 256>>>(offset_pred, offset_true, cls_true,
                                     vertical_true);

    final_reduce_kernel<<<1, 1024>>>(out);
}